// round 3
// baseline (speedup 1.0000x reference)
#include <cuda_runtime.h>
#include <cuda_bf16.h>
#include <cstdint>

// Problem constants
#define E_   8
#define T_   1024
#define H_   1024
#define F_   4096
#define DL_  256
#define NTOK (E_ * T_)   // 8192

// ---------------- device scratch ----------------
__device__ __nv_bfloat16 g_x_hi  [(size_t)NTOK * H_];
__device__ __nv_bfloat16 g_x_lo  [(size_t)NTOK * H_];
__device__ __nv_bfloat16 g_a_hi  [(size_t)NTOK * DL_];
__device__ __nv_bfloat16 g_a_lo  [(size_t)NTOK * DL_];
__device__ __nv_bfloat16 g_wup_hi[(size_t)E_ * F_ * DL_];
__device__ __nv_bfloat16 g_wup_lo[(size_t)E_ * F_ * DL_];
__device__ __nv_bfloat16 g_v1_hi [(size_t)E_ * F_ * H_];
__device__ __nv_bfloat16 g_v1_lo [(size_t)E_ * F_ * H_];
__device__ __nv_bfloat16 g_h_hi  [(size_t)E_ * T_ * F_];
__device__ __nv_bfloat16 g_h_lo  [(size_t)E_ * T_ * F_];
__device__ __nv_bfloat16 g_w2t_hi[(size_t)E_ * H_ * F_];
__device__ __nv_bfloat16 g_w2t_lo[(size_t)E_ * H_ * F_];

// ---------------- helpers ----------------
__device__ __forceinline__ uint32_t smem_u32(const void* p) {
    uint32_t a;
    asm("{ .reg .u64 t; cvta.to.shared.u64 t, %1; cvt.u32.u64 %0, t; }" : "=r"(a) : "l"(p));
    return a;
}
__device__ __forceinline__ void ldsm_x4(uint32_t (&r)[4], uint32_t addr) {
    asm volatile("ldmatrix.sync.aligned.m8n8.x4.shared.b16 {%0,%1,%2,%3}, [%4];"
        : "=r"(r[0]), "=r"(r[1]), "=r"(r[2]), "=r"(r[3]) : "r"(addr));
}
__device__ __forceinline__ void mma16816(float (&d)[4], const uint32_t (&a)[4],
                                         uint32_t b0, uint32_t b1) {
    asm volatile(
        "mma.sync.aligned.m16n8k16.row.col.f32.bf16.bf16.f32 "
        "{%0,%1,%2,%3}, {%4,%5,%6,%7}, {%8,%9}, {%0,%1,%2,%3};"
        : "+f"(d[0]), "+f"(d[1]), "+f"(d[2]), "+f"(d[3])
        : "r"(a[0]), "r"(a[1]), "r"(a[2]), "r"(a[3]), "r"(b0), "r"(b1));
}
__device__ __forceinline__ void cp16(uint32_t saddr, const void* g) {
    asm volatile("cp.async.cg.shared.global [%0], [%1], 16;" :: "r"(saddr), "l"(g));
}
#define CP_COMMIT() asm volatile("cp.async.commit_group;" ::: "memory")
#define CP_WAIT(N)  asm volatile("cp.async.wait_group %0;" :: "n"(N) : "memory")

__device__ __forceinline__ void split1(float v, __nv_bfloat16& h, __nv_bfloat16& l) {
    h = __float2bfloat16(v);
    l = __float2bfloat16(v - __bfloat162float(h));
}
__device__ __forceinline__ uint32_t pack_bf2(__nv_bfloat16 a, __nv_bfloat16 b) {
    __nv_bfloat162 t; t.x = a; t.y = b;
    return *reinterpret_cast<uint32_t*>(&t);
}
__device__ __forceinline__ float silu(float a) { return a / (1.0f + __expf(-a)); }

// ---------------- conversion kernels ----------------
__global__ void __launch_bounds__(256) split_convert(const float* __restrict__ src, int which, int n) {
    __nv_bfloat16 *hi, *lo;
    if      (which == 0) { hi = g_x_hi;   lo = g_x_lo; }
    else if (which == 1) { hi = g_a_hi;   lo = g_a_lo; }
    else if (which == 2) { hi = g_wup_hi; lo = g_wup_lo; }
    else                 { hi = g_v1_hi;  lo = g_v1_lo; }
    int i = (blockIdx.x * 256 + threadIdx.x) * 4;
    if (i >= n) return;
    float4 v = *reinterpret_cast<const float4*>(src + i);
    __nv_bfloat16 h0,h1,h2,h3,l0,l1,l2,l3;
    split1(v.x,h0,l0); split1(v.y,h1,l1); split1(v.z,h2,l2); split1(v.w,h3,l3);
    uint2 hv = make_uint2(pack_bf2(h0,h1), pack_bf2(h2,h3));
    uint2 lv = make_uint2(pack_bf2(l0,l1), pack_bf2(l2,l3));
    *reinterpret_cast<uint2*>(hi + i) = hv;
    *reinterpret_cast<uint2*>(lo + i) = lv;
}

__global__ void __launch_bounds__(256) transpose_convert_w2(const float* __restrict__ w2) {
    __shared__ float tile[32][33];
    int e = blockIdx.z;
    int f0 = blockIdx.x * 32, h0 = blockIdx.y * 32;
    int tx = threadIdx.x, ty = threadIdx.y;  // 32 x 8
#pragma unroll
    for (int r = 0; r < 4; r++) {
        int f = f0 + ty + r * 8;
        tile[ty + r * 8][tx] = w2[((size_t)e * F_ + f) * H_ + h0 + tx];
    }
    __syncthreads();
#pragma unroll
    for (int r = 0; r < 4; r++) {
        int h = h0 + ty + r * 8;
        float v = tile[tx][ty + r * 8];
        __nv_bfloat16 hi, lo; split1(v, hi, lo);
        size_t off = ((size_t)e * H_ + h) * F_ + f0 + tx;
        g_w2t_hi[off] = hi;
        g_w2t_lo[off] = lo;
    }
}

// ================= GLU kernel: CTA 128x128, warp 32x64, K-chunk 64, 3 stages =================
static constexpr int SA64 = 72;                        // row stride (bf16 elems), 144 B
static constexpr int T64_BYTES = 128 * SA64 * 2;       // 18432
static constexpr int STG_G = 4 * T64_BYTES;            // Ah, Al, Bh, Bl = 73728
static constexpr int SMEM_GLU = 3 * STG_G;             // 221184

// load a 128x64 bf16 K-major tile; 256 threads x 4 16B-chunks
__device__ __forceinline__ void load_t64(uint32_t sdst, const __nv_bfloat16* __restrict__ g,
                                         int ldg, int tid) {
#pragma unroll
    for (int i = 0; i < 4; i++) {
        int c = tid + i * 256;
        int row = c >> 3, col = (c & 7) * 8;
        cp16(sdst + (uint32_t)(row * SA64 + col) * 2, g + (size_t)row * ldg + col);
    }
}

// one K=64 stage for a 32x64 warp tile (3-term split)
__device__ __forceinline__ void mma_stage64(float (&acc)[2][8][4], uint32_t sb,
                                            int warp_m, int warp_n, int lane) {
    uint32_t sAh = sb, sAl = sb + T64_BYTES, sBh = sb + 2*T64_BYTES, sBl = sb + 3*T64_BYTES;
    int lrow = lane & 15, lk = (lane >> 4) * 8;
#pragma unroll
    for (int ks = 0; ks < 4; ks++) {
        int k = ks * 16 + lk;
        uint32_t ah[2][4], al[2][4], bh[4][4], bl[4][4];
#pragma unroll
        for (int mi = 0; mi < 2; mi++) {
            uint32_t off = (uint32_t)((warp_m * 32 + mi * 16 + lrow) * SA64 + k) * 2;
            ldsm_x4(ah[mi], sAh + off);
            ldsm_x4(al[mi], sAl + off);
        }
#pragma unroll
        for (int gj = 0; gj < 4; gj++) {
            uint32_t off = (uint32_t)((warp_n * 64 + gj * 16 + lrow) * SA64 + k) * 2;
            ldsm_x4(bh[gj], sBh + off);
            ldsm_x4(bl[gj], sBl + off);
        }
#pragma unroll
        for (int mi = 0; mi < 2; mi++)
#pragma unroll
        for (int gj = 0; gj < 4; gj++)
#pragma unroll
        for (int hh = 0; hh < 2; hh++) {
            int nj = gj * 2 + hh;
            mma16816(acc[mi][nj], ah[mi], bh[gj][hh], bh[gj][2 + hh]);
            mma16816(acc[mi][nj], ah[mi], bl[gj][hh], bl[gj][2 + hh]);
            mma16816(acc[mi][nj], al[mi], bh[gj][hh], bh[gj][2 + hh]);
        }
    }
}

__global__ void __launch_bounds__(256, 1) glu_kernel() {
    extern __shared__ char smem[];
    uint32_t sbase = smem_u32(smem);
    int tid = threadIdx.x, lane = tid & 31, wid = tid >> 5;
    int warp_m = wid & 3, warp_n = wid >> 2;     // 4 x 2 warps -> warp tile 32x64
    int e = blockIdx.z, m0 = blockIdx.y * 128, f0 = blockIdx.x * 128;

    const __nv_bfloat16* Aa_h = g_a_hi  + (size_t)(e * T_ + m0) * DL_;
    const __nv_bfloat16* Aa_l = g_a_lo  + (size_t)(e * T_ + m0) * DL_;
    const __nv_bfloat16* Bw_h = g_wup_hi + ((size_t)e * F_ + f0) * DL_;
    const __nv_bfloat16* Bw_l = g_wup_lo + ((size_t)e * F_ + f0) * DL_;
    const __nv_bfloat16* Ax_h = g_x_hi  + (size_t)(e * T_ + m0) * H_;
    const __nv_bfloat16* Ax_l = g_x_lo  + (size_t)(e * T_ + m0) * H_;
    const __nv_bfloat16* Bv_h = g_v1_hi + ((size_t)e * F_ + f0) * H_;
    const __nv_bfloat16* Bv_l = g_v1_lo + ((size_t)e * F_ + f0) * H_;

    // unified 20-chunk pipeline: kt 0..3 -> acts/wup (K=256); kt 4..19 -> x/v1 (K=1024)
    const int NK = 4 + 16;
    auto load_chunk = [&](int stage, int kt) {
        uint32_t sb = sbase + stage * STG_G;
        if (kt < 4) {
            load_t64(sb + 0 * T64_BYTES, Aa_h + kt * 64, DL_, tid);
            load_t64(sb + 1 * T64_BYTES, Aa_l + kt * 64, DL_, tid);
            load_t64(sb + 2 * T64_BYTES, Bw_h + kt * 64, DL_, tid);
            load_t64(sb + 3 * T64_BYTES, Bw_l + kt * 64, DL_, tid);
        } else {
            int k2 = kt - 4;
            load_t64(sb + 0 * T64_BYTES, Ax_h + k2 * 64, H_, tid);
            load_t64(sb + 1 * T64_BYTES, Ax_l + k2 * 64, H_, tid);
            load_t64(sb + 2 * T64_BYTES, Bv_h + k2 * 64, H_, tid);
            load_t64(sb + 3 * T64_BYTES, Bv_l + k2 * 64, H_, tid);
        }
    };

    float acc1[2][8][4], acc2[2][8][4];
#pragma unroll
    for (int i = 0; i < 2; i++)
#pragma unroll
        for (int j = 0; j < 8; j++)
#pragma unroll
            for (int k = 0; k < 4; k++) { acc1[i][j][k] = 0.f; acc2[i][j][k] = 0.f; }

    load_chunk(0, 0); CP_COMMIT();
    load_chunk(1, 1); CP_COMMIT();
    int ls = 2, cs = 0;
    for (int kt = 0; kt < NK; kt++) {
        if (kt + 2 < NK) { CP_WAIT(1); } else { CP_WAIT(0); }
        __syncthreads();
        if (kt + 2 < NK) {
            load_chunk(ls, kt + 2); CP_COMMIT();
            if (++ls == 3) ls = 0;
        }
        if (kt < 4) mma_stage64(acc1, sbase + cs * STG_G, warp_m, warp_n, lane);
        else        mma_stage64(acc2, sbase + cs * STG_G, warp_m, warp_n, lane);
        if (++cs == 3) cs = 0;
    }

    // epilogue: h = silu(acc1) * acc2 -> split bf16 hi/lo
    int gid = lane >> 2, q = lane & 3;
#pragma unroll
    for (int mi = 0; mi < 2; mi++)
#pragma unroll
    for (int nj = 0; nj < 8; nj++) {
        int m = m0 + warp_m * 32 + mi * 16 + gid;
        int n = f0 + warp_n * 64 + nj * 8 + q * 2;
        float s0 = silu(acc1[mi][nj][0]) * acc2[mi][nj][0];
        float s1 = silu(acc1[mi][nj][1]) * acc2[mi][nj][1];
        float s2 = silu(acc1[mi][nj][2]) * acc2[mi][nj][2];
        float s3 = silu(acc1[mi][nj][3]) * acc2[mi][nj][3];
        __nv_bfloat16 h0,l0,h1,l1,h2,l2,h3,l3;
        split1(s0,h0,l0); split1(s1,h1,l1); split1(s2,h2,l2); split1(s3,h3,l3);
        size_t off0 = ((size_t)(e * T_ + m)) * F_ + n;
        size_t off1 = ((size_t)(e * T_ + m + 8)) * F_ + n;
        *reinterpret_cast<uint32_t*>(g_h_hi + off0) = pack_bf2(h0, h1);
        *reinterpret_cast<uint32_t*>(g_h_lo + off0) = pack_bf2(l0, l1);
        *reinterpret_cast<uint32_t*>(g_h_hi + off1) = pack_bf2(h2, h3);
        *reinterpret_cast<uint32_t*>(g_h_lo + off1) = pack_bf2(l2, l3);
    }
}

// ================= GEMM3: out = h @ w2t, CTA 256x128, warp 64x64, K-chunk 32, 3 stages =================
static constexpr int SA32 = 40;                         // row stride (bf16), 80 B (16B-aligned)
static constexpr int A32_BYTES = 256 * SA32 * 2;        // 20480
static constexpr int B32_BYTES = 128 * SA32 * 2;        // 10240
static constexpr int STG_3 = 2 * A32_BYTES + 2 * B32_BYTES;  // 61440
static constexpr int SMEM_G3 = 3 * STG_3;               // 184320

// ROWS x 32 tile; ROWS*4 16B-chunks spread over 256 threads
template <int ROWS>
__device__ __forceinline__ void load_t32(uint32_t sdst, const __nv_bfloat16* __restrict__ g,
                                         int ldg, int tid) {
#pragma unroll
    for (int i = 0; i < ROWS * 4 / 256; i++) {
        int c = tid + i * 256;
        int row = c >> 2, col = (c & 3) * 8;
        cp16(sdst + (uint32_t)(row * SA32 + col) * 2, g + (size_t)row * ldg + col);
    }
}

__global__ void __launch_bounds__(256, 1) gemm3_kernel(float* __restrict__ out) {
    extern __shared__ char smem[];
    uint32_t sbase = smem_u32(smem);
    int tid = threadIdx.x, lane = tid & 31, wid = tid >> 5;
    int warp_m = wid & 3, warp_n = wid >> 2;     // 4 x 2 -> warp tile 64x64
    int e = blockIdx.z, m0 = blockIdx.y * 256, n0 = blockIdx.x * 128;

    const __nv_bfloat16* Ah = g_h_hi  + (size_t)(e * T_ + m0) * F_;
    const __nv_bfloat16* Al = g_h_lo  + (size_t)(e * T_ + m0) * F_;
    const __nv_bfloat16* Bh = g_w2t_hi + ((size_t)e * H_ + n0) * F_;
    const __nv_bfloat16* Bl = g_w2t_lo + ((size_t)e * H_ + n0) * F_;

    auto load_chunk = [&](int stage, int kt) {
        uint32_t sb = sbase + stage * STG_3;
        load_t32<256>(sb,                               Ah + kt * 32, F_, tid);
        load_t32<256>(sb + A32_BYTES,                   Al + kt * 32, F_, tid);
        load_t32<128>(sb + 2 * A32_BYTES,               Bh + kt * 32, F_, tid);
        load_t32<128>(sb + 2 * A32_BYTES + B32_BYTES,   Bl + kt * 32, F_, tid);
    };

    float acc[4][8][4];
#pragma unroll
    for (int i = 0; i < 4; i++)
#pragma unroll
        for (int j = 0; j < 8; j++)
#pragma unroll
            for (int k = 0; k < 4; k++) acc[i][j][k] = 0.f;

    const int NK = F_ / 32;   // 128
    load_chunk(0, 0); CP_COMMIT();
    load_chunk(1, 1); CP_COMMIT();
    int ls = 2, cs = 0;
    for (int kt = 0; kt < NK; kt++) {
        if (kt + 2 < NK) { CP_WAIT(1); } else { CP_WAIT(0); }
        __syncthreads();
        if (kt + 2 < NK) {
            load_chunk(ls, kt + 2); CP_COMMIT();
            if (++ls == 3) ls = 0;
        }
        // MMA on stage cs
        {
            uint32_t sb = sbase + cs * STG_3;
            uint32_t sAh = sb, sAl = sb + A32_BYTES;
            uint32_t sBh = sb + 2 * A32_BYTES, sBl = sBh + B32_BYTES;
            int lrow = lane & 15, lk = (lane >> 4) * 8;
#pragma unroll
            for (int ks = 0; ks < 2; ks++) {
                int k = ks * 16 + lk;
                uint32_t ah[4][4], al[4][4], bh[4][4], bl[4][4];
#pragma unroll
                for (int mi = 0; mi < 4; mi++) {
                    uint32_t off = (uint32_t)((warp_m * 64 + mi * 16 + lrow) * SA32 + k) * 2;
                    ldsm_x4(ah[mi], sAh + off);
                    ldsm_x4(al[mi], sAl + off);
                }
#pragma unroll
                for (int gj = 0; gj < 4; gj++) {
                    uint32_t off = (uint32_t)((warp_n * 64 + gj * 16 + lrow) * SA32 + k) * 2;
                    ldsm_x4(bh[gj], sBh + off);
                    ldsm_x4(bl[gj], sBl + off);
                }
#pragma unroll
                for (int mi = 0; mi < 4; mi++)
#pragma unroll
                for (int gj = 0; gj < 4; gj++)
#pragma unroll
                for (int hh = 0; hh < 2; hh++) {
                    int nj = gj * 2 + hh;
                    mma16816(acc[mi][nj], ah[mi], bh[gj][hh], bh[gj][2 + hh]);
                    mma16816(acc[mi][nj], ah[mi], bl[gj][hh], bl[gj][2 + hh]);
                    mma16816(acc[mi][nj], al[mi], bh[gj][hh], bh[gj][2 + hh]);
                }
            }
        }
        if (++cs == 3) cs = 0;
    }

    int gid = lane >> 2, q = lane & 3;
#pragma unroll
    for (int mi = 0; mi < 4; mi++)
#pragma unroll
    for (int nj = 0; nj < 8; nj++) {
        int m = m0 + warp_m * 64 + mi * 16 + gid;
        int n = n0 + warp_n * 64 + nj * 8 + q * 2;
        size_t off0 = ((size_t)(e * T_ + m)) * H_ + n;
        size_t off1 = ((size_t)(e * T_ + m + 8)) * H_ + n;
        *reinterpret_cast<float2*>(out + off0) = make_float2(acc[mi][nj][0], acc[mi][nj][1]);
        *reinterpret_cast<float2*>(out + off1) = make_float2(acc[mi][nj][2], acc[mi][nj][3]);
    }
}

// ---------------- launch ----------------
extern "C" void kernel_launch(void* const* d_in, const int* in_sizes, int n_in,
                              void* d_out, int out_size) {
    const float* x    = (const float*)d_in[0];  // [8192, 1024]
    const float* acts = (const float*)d_in[1];  // [8192, 256]
    const float* wup  = (const float*)d_in[2];  // [8, 4096, 256]
    const float* v1   = (const float*)d_in[3];  // [8, 4096, 1024]
    const float* w2   = (const float*)d_in[4];  // [8, 4096, 1024]
    float* out = (float*)d_out;                 // [8192, 1024]

    cudaFuncSetAttribute(glu_kernel,   cudaFuncAttributeMaxDynamicSharedMemorySize, SMEM_GLU);
    cudaFuncSetAttribute(gemm3_kernel, cudaFuncAttributeMaxDynamicSharedMemorySize, SMEM_G3);

    // conversions
    {
        int n;
        n = NTOK * H_;     split_convert<<<n / 4 / 256, 256>>>(x,    0, n);
        n = NTOK * DL_;    split_convert<<<n / 4 / 256, 256>>>(acts, 1, n);
        n = E_ * F_ * DL_; split_convert<<<n / 4 / 256, 256>>>(wup,  2, n);
        n = E_ * F_ * H_;  split_convert<<<n / 4 / 256, 256>>>(v1,   3, n);
        dim3 tg(F_ / 32, H_ / 32, E_);
        transpose_convert_w2<<<tg, dim3(32, 8)>>>(w2);
    }

    // fused GLU
    {
        dim3 grid(F_ / 128, T_ / 128, E_);
        glu_kernel<<<grid, 256, SMEM_GLU>>>();
    }

    // out = h @ w2
    {
        dim3 grid(H_ / 128, T_ / 256, E_);
        gemm3_kernel<<<grid, 256, SMEM_G3>>>(out);
    }
}

// round 4
// speedup vs baseline: 2.2970x; 2.2970x over previous
#include <cuda_runtime.h>
#include <cuda_fp16.h>
#include <cstdint>

// Problem constants
#define E_   8
#define T_   1024
#define H_   1024
#define F_   4096
#define DL_  256
#define NTOK (E_ * T_)   // 8192

// ---------------- device scratch ----------------
__device__ __half g_x  [(size_t)NTOK * H_];
__device__ __half g_a  [(size_t)NTOK * DL_];
__device__ __half g_wup[(size_t)E_ * F_ * DL_];
__device__ __half g_v1 [(size_t)E_ * F_ * H_];
__device__ __half g_h  [(size_t)E_ * T_ * F_];
__device__ __half g_w2t[(size_t)E_ * H_ * F_];

// ---------------- helpers ----------------
__device__ __forceinline__ uint32_t smem_u32(const void* p) {
    uint32_t a;
    asm("{ .reg .u64 t; cvta.to.shared.u64 t, %1; cvt.u32.u64 %0, t; }" : "=r"(a) : "l"(p));
    return a;
}
__device__ __forceinline__ void ldsm_x4(uint32_t (&r)[4], uint32_t addr) {
    asm volatile("ldmatrix.sync.aligned.m8n8.x4.shared.b16 {%0,%1,%2,%3}, [%4];"
        : "=r"(r[0]), "=r"(r[1]), "=r"(r[2]), "=r"(r[3]) : "r"(addr));
}
__device__ __forceinline__ void mma16816(float (&d)[4], const uint32_t (&a)[4],
                                         uint32_t b0, uint32_t b1) {
    asm volatile(
        "mma.sync.aligned.m16n8k16.row.col.f32.f16.f16.f32 "
        "{%0,%1,%2,%3}, {%4,%5,%6,%7}, {%8,%9}, {%0,%1,%2,%3};"
        : "+f"(d[0]), "+f"(d[1]), "+f"(d[2]), "+f"(d[3])
        : "r"(a[0]), "r"(a[1]), "r"(a[2]), "r"(a[3]), "r"(b0), "r"(b1));
}
__device__ __forceinline__ void cp16(uint32_t saddr, const void* g) {
    asm volatile("cp.async.cg.shared.global [%0], [%1], 16;" :: "r"(saddr), "l"(g));
}
#define CP_COMMIT() asm volatile("cp.async.commit_group;" ::: "memory")
#define CP_WAIT(N)  asm volatile("cp.async.wait_group %0;" :: "n"(N) : "memory")

__device__ __forceinline__ uint32_t pack_h2(__half a, __half b) {
    __half2 t; t.x = a; t.y = b;
    return *reinterpret_cast<uint32_t*>(&t);
}
__device__ __forceinline__ float silu(float a) { return a / (1.0f + __expf(-a)); }

// ---------------- conversion kernels ----------------
// which: 0=x, 1=acts, 2=wup, 3=v1
__global__ void __launch_bounds__(256) conv_f16(const float* __restrict__ src, int which, int n) {
    __half* dst;
    if      (which == 0) dst = g_x;
    else if (which == 1) dst = g_a;
    else if (which == 2) dst = g_wup;
    else                 dst = g_v1;
    int i = (blockIdx.x * 256 + threadIdx.x) * 8;
    if (i >= n) return;
    float4 v0 = *reinterpret_cast<const float4*>(src + i);
    float4 v1 = *reinterpret_cast<const float4*>(src + i + 4);
    uint4 o;
    o.x = pack_h2(__float2half_rn(v0.x), __float2half_rn(v0.y));
    o.y = pack_h2(__float2half_rn(v0.z), __float2half_rn(v0.w));
    o.z = pack_h2(__float2half_rn(v1.x), __float2half_rn(v1.y));
    o.w = pack_h2(__float2half_rn(v1.z), __float2half_rn(v1.w));
    *reinterpret_cast<uint4*>(dst + i) = o;
}

// w2 [E,F,H] -> w2t [E,H,F] fp16
__global__ void __launch_bounds__(256) transpose_convert_w2(const float* __restrict__ w2) {
    __shared__ float tile[32][33];
    int e = blockIdx.z;
    int f0 = blockIdx.x * 32, h0 = blockIdx.y * 32;
    int tx = threadIdx.x, ty = threadIdx.y;  // 32 x 8
#pragma unroll
    for (int r = 0; r < 4; r++) {
        int f = f0 + ty + r * 8;
        tile[ty + r * 8][tx] = w2[((size_t)e * F_ + f) * H_ + h0 + tx];
    }
    __syncthreads();
#pragma unroll
    for (int r = 0; r < 4; r++) {
        int h = h0 + ty + r * 8;
        float v = tile[tx][ty + r * 8];
        g_w2t[((size_t)e * H_ + h) * F_ + f0 + tx] = __float2half_rn(v);
    }
}

// ================= GLU kernel: CTA 128x128, warp 32x64, K-chunk 64, 3 stages =================
static constexpr int SA64 = 72;                        // row stride (fp16 elems), 144 B
static constexpr int T64_BYTES = 128 * SA64 * 2;       // 18432
static constexpr int STG_G = 2 * T64_BYTES;            // A, B = 36864
static constexpr int SMEM_GLU = 3 * STG_G;             // 110592

__device__ __forceinline__ void load_t64(uint32_t sdst, const __half* __restrict__ g,
                                         int ldg, int tid) {
#pragma unroll
    for (int i = 0; i < 4; i++) {
        int c = tid + i * 256;
        int row = c >> 3, col = (c & 7) * 8;
        cp16(sdst + (uint32_t)(row * SA64 + col) * 2, g + (size_t)row * ldg + col);
    }
}

// one K=64 stage for a 32x64 warp tile (single-pass fp16)
__device__ __forceinline__ void mma_stage64(float (&acc)[2][8][4], uint32_t sb,
                                            int warp_m, int warp_n, int lane) {
    uint32_t sA = sb, sB = sb + T64_BYTES;
    int lrow = lane & 15, lk = (lane >> 4) * 8;
#pragma unroll
    for (int ks = 0; ks < 4; ks++) {
        int k = ks * 16 + lk;
        uint32_t a[2][4], b[4][4];
#pragma unroll
        for (int mi = 0; mi < 2; mi++) {
            uint32_t off = (uint32_t)((warp_m * 32 + mi * 16 + lrow) * SA64 + k) * 2;
            ldsm_x4(a[mi], sA + off);
        }
#pragma unroll
        for (int gj = 0; gj < 4; gj++) {
            uint32_t off = (uint32_t)((warp_n * 64 + gj * 16 + lrow) * SA64 + k) * 2;
            ldsm_x4(b[gj], sB + off);
        }
#pragma unroll
        for (int mi = 0; mi < 2; mi++)
#pragma unroll
        for (int gj = 0; gj < 4; gj++)
#pragma unroll
        for (int hh = 0; hh < 2; hh++)
            mma16816(acc[mi][gj * 2 + hh], a[mi], b[gj][hh], b[gj][2 + hh]);
    }
}

__global__ void __launch_bounds__(256, 1) glu_kernel() {
    extern __shared__ char smem[];
    uint32_t sbase = smem_u32(smem);
    int tid = threadIdx.x, lane = tid & 31, wid = tid >> 5;
    int warp_m = wid & 3, warp_n = wid >> 2;     // 4 x 2 warps -> warp tile 32x64
    int e = blockIdx.z, m0 = blockIdx.y * 128, f0 = blockIdx.x * 128;

    const __half* Aa = g_a   + (size_t)(e * T_ + m0) * DL_;
    const __half* Bw = g_wup + ((size_t)e * F_ + f0) * DL_;
    const __half* Ax = g_x   + (size_t)(e * T_ + m0) * H_;
    const __half* Bv = g_v1  + ((size_t)e * F_ + f0) * H_;

    // unified 20-chunk pipeline: kt 0..3 -> acts/wup (K=256); kt 4..19 -> x/v1 (K=1024)
    const int NK = 4 + 16;
    auto load_chunk = [&](int stage, int kt) {
        uint32_t sb = sbase + stage * STG_G;
        if (kt < 4) {
            load_t64(sb,             Aa + kt * 64, DL_, tid);
            load_t64(sb + T64_BYTES, Bw + kt * 64, DL_, tid);
        } else {
            int k2 = kt - 4;
            load_t64(sb,             Ax + k2 * 64, H_, tid);
            load_t64(sb + T64_BYTES, Bv + k2 * 64, H_, tid);
        }
    };

    float acc1[2][8][4], acc2[2][8][4];
#pragma unroll
    for (int i = 0; i < 2; i++)
#pragma unroll
        for (int j = 0; j < 8; j++)
#pragma unroll
            for (int k = 0; k < 4; k++) { acc1[i][j][k] = 0.f; acc2[i][j][k] = 0.f; }

    load_chunk(0, 0); CP_COMMIT();
    load_chunk(1, 1); CP_COMMIT();
    int ls = 2, cs = 0;
    for (int kt = 0; kt < NK; kt++) {
        if (kt + 2 < NK) { CP_WAIT(1); } else { CP_WAIT(0); }
        __syncthreads();
        if (kt + 2 < NK) {
            load_chunk(ls, kt + 2); CP_COMMIT();
            if (++ls == 3) ls = 0;
        }
        if (kt < 4) mma_stage64(acc1, sbase + cs * STG_G, warp_m, warp_n, lane);
        else        mma_stage64(acc2, sbase + cs * STG_G, warp_m, warp_n, lane);
        if (++cs == 3) cs = 0;
    }

    // epilogue: h = silu(acc1) * acc2 -> fp16
    int gid = lane >> 2, q = lane & 3;
#pragma unroll
    for (int mi = 0; mi < 2; mi++)
#pragma unroll
    for (int nj = 0; nj < 8; nj++) {
        int m = m0 + warp_m * 32 + mi * 16 + gid;
        int n = f0 + warp_n * 64 + nj * 8 + q * 2;
        float s0 = silu(acc1[mi][nj][0]) * acc2[mi][nj][0];
        float s1 = silu(acc1[mi][nj][1]) * acc2[mi][nj][1];
        float s2 = silu(acc1[mi][nj][2]) * acc2[mi][nj][2];
        float s3 = silu(acc1[mi][nj][3]) * acc2[mi][nj][3];
        size_t off0 = ((size_t)(e * T_ + m)) * F_ + n;
        size_t off1 = ((size_t)(e * T_ + m + 8)) * F_ + n;
        *reinterpret_cast<uint32_t*>(g_h + off0) = pack_h2(__float2half_rn(s0), __float2half_rn(s1));
        *reinterpret_cast<uint32_t*>(g_h + off1) = pack_h2(__float2half_rn(s2), __float2half_rn(s3));
    }
}

// ================= GEMM3: out = h @ w2t, CTA 256x128, warp 64x64, K-chunk 32, 3 stages =================
static constexpr int SA32 = 40;                         // row stride (fp16), 80 B
static constexpr int A32_BYTES = 256 * SA32 * 2;        // 20480
static constexpr int B32_BYTES = 128 * SA32 * 2;        // 10240
static constexpr int STG_3 = A32_BYTES + B32_BYTES;     // 30720
static constexpr int SMEM_G3 = 3 * STG_3;               // 92160

template <int ROWS>
__device__ __forceinline__ void load_t32(uint32_t sdst, const __half* __restrict__ g,
                                         int ldg, int tid) {
#pragma unroll
    for (int i = 0; i < ROWS * 4 / 256; i++) {
        int c = tid + i * 256;
        int row = c >> 2, col = (c & 3) * 8;
        cp16(sdst + (uint32_t)(row * SA32 + col) * 2, g + (size_t)row * ldg + col);
    }
}

__global__ void __launch_bounds__(256, 1) gemm3_kernel(float* __restrict__ out) {
    extern __shared__ char smem[];
    uint32_t sbase = smem_u32(smem);
    int tid = threadIdx.x, lane = tid & 31, wid = tid >> 5;
    int warp_m = wid & 3, warp_n = wid >> 2;     // 4 x 2 -> warp tile 64x64
    int e = blockIdx.z, m0 = blockIdx.y * 256, n0 = blockIdx.x * 128;

    const __half* Ah = g_h   + (size_t)(e * T_ + m0) * F_;
    const __half* Bh = g_w2t + ((size_t)e * H_ + n0) * F_;

    auto load_chunk = [&](int stage, int kt) {
        uint32_t sb = sbase + stage * STG_3;
        load_t32<256>(sb,             Ah + kt * 32, F_, tid);
        load_t32<128>(sb + A32_BYTES, Bh + kt * 32, F_, tid);
    };

    float acc[4][8][4];
#pragma unroll
    for (int i = 0; i < 4; i++)
#pragma unroll
        for (int j = 0; j < 8; j++)
#pragma unroll
            for (int k = 0; k < 4; k++) acc[i][j][k] = 0.f;

    const int NK = F_ / 32;   // 128
    load_chunk(0, 0); CP_COMMIT();
    load_chunk(1, 1); CP_COMMIT();
    int ls = 2, cs = 0;
    for (int kt = 0; kt < NK; kt++) {
        if (kt + 2 < NK) { CP_WAIT(1); } else { CP_WAIT(0); }
        __syncthreads();
        if (kt + 2 < NK) {
            load_chunk(ls, kt + 2); CP_COMMIT();
            if (++ls == 3) ls = 0;
        }
        {
            uint32_t sb = sbase + cs * STG_3;
            uint32_t sA = sb, sB = sb + A32_BYTES;
            int lrow = lane & 15, lk = (lane >> 4) * 8;
#pragma unroll
            for (int ks = 0; ks < 2; ks++) {
                int k = ks * 16 + lk;
                uint32_t a[4][4], b[4][4];
#pragma unroll
                for (int mi = 0; mi < 4; mi++) {
                    uint32_t off = (uint32_t)((warp_m * 64 + mi * 16 + lrow) * SA32 + k) * 2;
                    ldsm_x4(a[mi], sA + off);
                }
#pragma unroll
                for (int gj = 0; gj < 4; gj++) {
                    uint32_t off = (uint32_t)((warp_n * 64 + gj * 16 + lrow) * SA32 + k) * 2;
                    ldsm_x4(b[gj], sB + off);
                }
#pragma unroll
                for (int mi = 0; mi < 4; mi++)
#pragma unroll
                for (int gj = 0; gj < 4; gj++)
#pragma unroll
                for (int hh = 0; hh < 2; hh++)
                    mma16816(acc[mi][gj * 2 + hh], a[mi], b[gj][hh], b[gj][2 + hh]);
            }
        }
        if (++cs == 3) cs = 0;
    }

    int gid = lane >> 2, q = lane & 3;
#pragma unroll
    for (int mi = 0; mi < 4; mi++)
#pragma unroll
    for (int nj = 0; nj < 8; nj++) {
        int m = m0 + warp_m * 64 + mi * 16 + gid;
        int n = n0 + warp_n * 64 + nj * 8 + q * 2;
        size_t off0 = ((size_t)(e * T_ + m)) * H_ + n;
        size_t off1 = ((size_t)(e * T_ + m + 8)) * H_ + n;
        *reinterpret_cast<float2*>(out + off0) = make_float2(acc[mi][nj][0], acc[mi][nj][1]);
        *reinterpret_cast<float2*>(out + off1) = make_float2(acc[mi][nj][2], acc[mi][nj][3]);
    }
}

// ---------------- launch ----------------
extern "C" void kernel_launch(void* const* d_in, const int* in_sizes, int n_in,
                              void* d_out, int out_size) {
    const float* x    = (const float*)d_in[0];  // [8192, 1024]
    const float* acts = (const float*)d_in[1];  // [8192, 256]
    const float* wup  = (const float*)d_in[2];  // [8, 4096, 256]
    const float* v1   = (const float*)d_in[3];  // [8, 4096, 1024]
    const float* w2   = (const float*)d_in[4];  // [8, 4096, 1024]
    float* out = (float*)d_out;                 // [8192, 1024]

    cudaFuncSetAttribute(glu_kernel,   cudaFuncAttributeMaxDynamicSharedMemorySize, SMEM_GLU);
    cudaFuncSetAttribute(gemm3_kernel, cudaFuncAttributeMaxDynamicSharedMemorySize, SMEM_G3);

    // conversions
    {
        int n;
        n = NTOK * H_;     conv_f16<<<n / 8 / 256, 256>>>(x,    0, n);
        n = NTOK * DL_;    conv_f16<<<n / 8 / 256, 256>>>(acts, 1, n);
        n = E_ * F_ * DL_; conv_f16<<<n / 8 / 256, 256>>>(wup,  2, n);
        n = E_ * F_ * H_;  conv_f16<<<n / 8 / 256, 256>>>(v1,   3, n);
        dim3 tg(F_ / 32, H_ / 32, E_);
        transpose_convert_w2<<<tg, dim3(32, 8)>>>(w2);
    }

    // fused GLU
    {
        dim3 grid(F_ / 128, T_ / 128, E_);
        glu_kernel<<<grid, 256, SMEM_GLU>>>();
    }

    // out = h @ w2
    {
        dim3 grid(H_ / 128, T_ / 256, E_);
        gemm3_kernel<<<grid, 256, SMEM_G3>>>(out);
    }
}

// round 5
// speedup vs baseline: 2.3518x; 1.0238x over previous
#include <cuda_runtime.h>
#include <cuda_fp16.h>
#include <cstdint>

// Problem constants
#define E_   8
#define T_   1024
#define H_   1024
#define F_   4096
#define DL_  256
#define NTOK (E_ * T_)   // 8192

// ---------------- device scratch ----------------
__device__ __half g_x  [(size_t)NTOK * H_];
__device__ __half g_a  [(size_t)NTOK * DL_];
__device__ __half g_wup[(size_t)E_ * F_ * DL_];
__device__ __half g_v1 [(size_t)E_ * F_ * H_];
__device__ __half g_h  [(size_t)E_ * T_ * F_];
__device__ __half g_w2t[(size_t)E_ * H_ * F_];

// ---------------- helpers ----------------
__device__ __forceinline__ uint32_t smem_u32(const void* p) {
    uint32_t a;
    asm("{ .reg .u64 t; cvta.to.shared.u64 t, %1; cvt.u32.u64 %0, t; }" : "=r"(a) : "l"(p));
    return a;
}
__device__ __forceinline__ void ldsm_x4(uint32_t (&r)[4], uint32_t addr) {
    asm volatile("ldmatrix.sync.aligned.m8n8.x4.shared.b16 {%0,%1,%2,%3}, [%4];"
        : "=r"(r[0]), "=r"(r[1]), "=r"(r[2]), "=r"(r[3]) : "r"(addr));
}
__device__ __forceinline__ void mma16816(float (&d)[4], const uint32_t (&a)[4],
                                         uint32_t b0, uint32_t b1) {
    asm volatile(
        "mma.sync.aligned.m16n8k16.row.col.f32.f16.f16.f32 "
        "{%0,%1,%2,%3}, {%4,%5,%6,%7}, {%8,%9}, {%0,%1,%2,%3};"
        : "+f"(d[0]), "+f"(d[1]), "+f"(d[2]), "+f"(d[3])
        : "r"(a[0]), "r"(a[1]), "r"(a[2]), "r"(a[3]), "r"(b0), "r"(b1));
}
__device__ __forceinline__ void cp16(uint32_t saddr, const void* g) {
    asm volatile("cp.async.cg.shared.global [%0], [%1], 16;" :: "r"(saddr), "l"(g));
}
#define CP_COMMIT() asm volatile("cp.async.commit_group;" ::: "memory")
#define CP_WAIT(N)  asm volatile("cp.async.wait_group %0;" :: "n"(N) : "memory")

__device__ __forceinline__ uint32_t pack_h2(__half a, __half b) {
    __half2 t; t.x = a; t.y = b;
    return *reinterpret_cast<uint32_t*>(&t);
}
__device__ __forceinline__ float silu(float a) { return a / (1.0f + __expf(-a)); }

// ---------------- fused conversion kernel (x, acts, wup, v1) ----------------
static constexpr size_t CB0 = (size_t)NTOK * H_ / 8;            // 1048576
static constexpr size_t CB1 = CB0 + (size_t)NTOK * DL_ / 8;     // +262144
static constexpr size_t CB2 = CB1 + (size_t)E_ * F_ * DL_ / 8;  // +1048576
static constexpr size_t CB3 = CB2 + (size_t)E_ * F_ * H_ / 8;   // +4194304 = 6553600

__global__ void __launch_bounds__(256) conv_all(const float* __restrict__ x,
                                                const float* __restrict__ a,
                                                const float* __restrict__ w,
                                                const float* __restrict__ v) {
    size_t it = (size_t)blockIdx.x * 256 + threadIdx.x;
    const float* s; __half* d; size_t off;
    if      (it < CB0) { s = x; d = g_x;   off = it; }
    else if (it < CB1) { s = a; d = g_a;   off = it - CB0; }
    else if (it < CB2) { s = w; d = g_wup; off = it - CB1; }
    else               { s = v; d = g_v1;  off = it - CB2; }
    size_t i = off * 8;
    float4 v0 = *reinterpret_cast<const float4*>(s + i);
    float4 v1 = *reinterpret_cast<const float4*>(s + i + 4);
    uint4 o;
    o.x = pack_h2(__float2half_rn(v0.x), __float2half_rn(v0.y));
    o.y = pack_h2(__float2half_rn(v0.z), __float2half_rn(v0.w));
    o.z = pack_h2(__float2half_rn(v1.x), __float2half_rn(v1.y));
    o.w = pack_h2(__float2half_rn(v1.z), __float2half_rn(v1.w));
    *reinterpret_cast<uint4*>(d + i) = o;
}

// w2 [E,F,H] -> w2t [E,H,F] fp16, fully coalesced (64f x 32h tiles, half2 stores)
__global__ void __launch_bounds__(256) transpose_convert_w2(const float* __restrict__ w2) {
    __shared__ float tile[64][33];
    int e = blockIdx.z;
    int f0 = blockIdx.x * 64, h0 = blockIdx.y * 32;
    int tx = threadIdx.x, ty = threadIdx.y;  // 32 x 8
#pragma unroll
    for (int r = 0; r < 8; r++) {
        int fr = ty + r * 8;
        tile[fr][tx] = w2[((size_t)e * F_ + f0 + fr) * H_ + h0 + tx];
    }
    __syncthreads();
#pragma unroll
    for (int r = 0; r < 4; r++) {
        int h = ty + r * 8;
        uint32_t p = pack_h2(__float2half_rn(tile[2 * tx][h]),
                             __float2half_rn(tile[2 * tx + 1][h]));
        *reinterpret_cast<uint32_t*>(&g_w2t[((size_t)e * H_ + h0 + h) * F_ + f0 + 2 * tx]) = p;
    }
}

// ================= shared GEMM pieces =================
static constexpr int SA64 = 72;                        // row stride (fp16), 144 B
static constexpr int TA_BYTES  = 128 * SA64 * 2;       // 18432 (128-row tile)
static constexpr int TB64_BYTES = 64 * SA64 * 2;       // 9216  (64-row tile)

// load a ROWSx64 fp16 K-major tile; 256 threads, 16B chunks
template <int ROWS>
__device__ __forceinline__ void load_t64(uint32_t sdst, const __half* __restrict__ g,
                                         int ldg, int tid) {
#pragma unroll
    for (int i = 0; i < ROWS * 8 / 256; i++) {
        int c = tid + i * 256;
        int row = c >> 3, col = (c & 7) * 8;
        cp16(sdst + (uint32_t)(row * SA64 + col) * 2, g + (size_t)row * ldg + col);
    }
}

// ================= GLU persistent kernel: tile 128x128, warp 32x64, K-chunk 64 =================
static constexpr int STG_G   = 2 * TA_BYTES;   // 36864
static constexpr int SMEM_GLU = 3 * STG_G;     // 110592
static constexpr int NT_GLU  = (T_ / 128) * (F_ / 128) * E_;   // 2048
static constexpr int NWORK   = 148;

__device__ __forceinline__ void mma_stage_glu(float (&acc)[2][8][4], uint32_t sb,
                                              int warp_m, int warp_n, int lane) {
    uint32_t sA = sb, sB = sb + TA_BYTES;
    int lrow = lane & 15, lk = (lane >> 4) * 8;
#pragma unroll
    for (int ks = 0; ks < 4; ks++) {
        int k = ks * 16 + lk;
        uint32_t a[2][4], b[4][4];
#pragma unroll
        for (int mi = 0; mi < 2; mi++)
            ldsm_x4(a[mi], sA + (uint32_t)((warp_m * 32 + mi * 16 + lrow) * SA64 + k) * 2);
#pragma unroll
        for (int gj = 0; gj < 4; gj++)
            ldsm_x4(b[gj], sB + (uint32_t)((warp_n * 64 + gj * 16 + lrow) * SA64 + k) * 2);
#pragma unroll
        for (int mi = 0; mi < 2; mi++)
#pragma unroll
        for (int gj = 0; gj < 4; gj++)
#pragma unroll
        for (int hh = 0; hh < 2; hh++)
            mma16816(acc[mi][gj * 2 + hh], a[mi], b[gj][hh], b[gj][2 + hh]);
    }
}

__global__ void __launch_bounds__(256, 1) glu_kernel() {
    extern __shared__ char smem[];
    uint32_t sbase = smem_u32(smem);
    int tid = threadIdx.x, lane = tid & 31, wid = tid >> 5;
    int warp_m = wid & 3, warp_n = wid >> 2;
    int bid = blockIdx.x;

    // ---- loader state (2 chunks ahead, flat stream across tiles) ----
    int lt = bid, lk = 0, ls = 0;
    const __half *LAa, *LBw, *LAx, *LBv;
    auto set_lptrs = [&](int t) {
        int e = t >> 8, r = t & 255;
        int m0 = (r >> 5) * 128, f0 = (r & 31) * 128;
        LAa = g_a   + (size_t)(e * T_ + m0) * DL_;
        LBw = g_wup + ((size_t)e * F_ + f0) * DL_;
        LAx = g_x   + (size_t)(e * T_ + m0) * H_;
        LBv = g_v1  + ((size_t)e * F_ + f0) * H_;
    };
    if (lt < NT_GLU) set_lptrs(lt);
    auto issue = [&]() {
        uint32_t sb = sbase + ls * STG_G;
        if (lt < NT_GLU) {
            if (lk < 4) {
                load_t64<128>(sb,            LAa + lk * 64, DL_, tid);
                load_t64<128>(sb + TA_BYTES, LBw + lk * 64, DL_, tid);
            } else {
                int k2 = lk - 4;
                load_t64<128>(sb,            LAx + k2 * 64, H_, tid);
                load_t64<128>(sb + TA_BYTES, LBv + k2 * 64, H_, tid);
            }
        }
        CP_COMMIT();   // empty group when lt >= NT_GLU — keeps wait counts uniform
        if (++ls == 3) ls = 0;
        if (++lk == 20) { lk = 0; lt += NWORK; if (lt < NT_GLU) set_lptrs(lt); }
    };
    issue(); issue();

    int cs = 0;
    for (int ct = bid; ct < NT_GLU; ct += NWORK) {
        int e = ct >> 8, r = ct & 255;
        int m0 = (r >> 5) * 128, f0 = (r & 31) * 128;

        float acc1[2][8][4], acc2[2][8][4];
#pragma unroll
        for (int i = 0; i < 2; i++)
#pragma unroll
            for (int j = 0; j < 8; j++)
#pragma unroll
                for (int k = 0; k < 4; k++) { acc1[i][j][k] = 0.f; acc2[i][j][k] = 0.f; }

        for (int kt = 0; kt < 20; kt++) {
            CP_WAIT(1);
            __syncthreads();
            issue();
            if (kt < 4) mma_stage_glu(acc1, sbase + cs * STG_G, warp_m, warp_n, lane);
            else        mma_stage_glu(acc2, sbase + cs * STG_G, warp_m, warp_n, lane);
            if (++cs == 3) cs = 0;
        }

        // epilogue (overlaps next tile's in-flight loads)
        int gid = lane >> 2, q = lane & 3;
#pragma unroll
        for (int mi = 0; mi < 2; mi++)
#pragma unroll
        for (int nj = 0; nj < 8; nj++) {
            int m = m0 + warp_m * 32 + mi * 16 + gid;
            int n = f0 + warp_n * 64 + nj * 8 + q * 2;
            float s0 = silu(acc1[mi][nj][0]) * acc2[mi][nj][0];
            float s1 = silu(acc1[mi][nj][1]) * acc2[mi][nj][1];
            float s2 = silu(acc1[mi][nj][2]) * acc2[mi][nj][2];
            float s3 = silu(acc1[mi][nj][3]) * acc2[mi][nj][3];
            size_t off0 = ((size_t)(e * T_ + m)) * F_ + n;
            size_t off1 = ((size_t)(e * T_ + m + 8)) * F_ + n;
            *reinterpret_cast<uint32_t*>(g_h + off0) = pack_h2(__float2half_rn(s0), __float2half_rn(s1));
            *reinterpret_cast<uint32_t*>(g_h + off1) = pack_h2(__float2half_rn(s2), __float2half_rn(s3));
        }
    }
}

// ================= GEMM3 persistent: tile 128x64, warp 32x32, K-chunk 64 =================
static constexpr int STG_3   = TA_BYTES + TB64_BYTES;  // 27648
static constexpr int SMEM_G3 = 3 * STG_3;              // 82944
static constexpr int NT_G3   = (T_ / 128) * (H_ / 64) * E_;  // 1024
static constexpr int NKC_G3  = F_ / 64;                // 64 chunks per tile

__global__ void __launch_bounds__(256, 1) gemm3_kernel(float* __restrict__ out) {
    extern __shared__ char smem[];
    uint32_t sbase = smem_u32(smem);
    int tid = threadIdx.x, lane = tid & 31, wid = tid >> 5;
    int warp_m = wid & 3, warp_n = wid >> 2;   // 4 x 2 -> warp tile 32x32
    int bid = blockIdx.x;

    int lt = bid, lk = 0, ls = 0;
    const __half *LA, *LB;
    auto set_lptrs = [&](int t) {
        int e = t >> 7, r = t & 127;
        int m0 = (r >> 4) * 128, n0 = (r & 15) * 64;
        LA = g_h   + (size_t)(e * T_ + m0) * F_;
        LB = g_w2t + ((size_t)e * H_ + n0) * F_;
    };
    if (lt < NT_G3) set_lptrs(lt);
    auto issue = [&]() {
        uint32_t sb = sbase + ls * STG_3;
        if (lt < NT_G3) {
            load_t64<128>(sb,            LA + lk * 64, F_, tid);
            load_t64<64> (sb + TA_BYTES, LB + lk * 64, F_, tid);
        }
        CP_COMMIT();
        if (++ls == 3) ls = 0;
        if (++lk == NKC_G3) { lk = 0; lt += NWORK; if (lt < NT_G3) set_lptrs(lt); }
    };
    issue(); issue();

    int cs = 0;
    for (int ct = bid; ct < NT_G3; ct += NWORK) {
        int e = ct >> 7, r = ct & 127;
        int m0 = (r >> 4) * 128, n0 = (r & 15) * 64;

        float acc[2][4][4];
#pragma unroll
        for (int i = 0; i < 2; i++)
#pragma unroll
            for (int j = 0; j < 4; j++)
#pragma unroll
                for (int k = 0; k < 4; k++) acc[i][j][k] = 0.f;

        for (int kt = 0; kt < NKC_G3; kt++) {
            CP_WAIT(1);
            __syncthreads();
            issue();
            {
                uint32_t sb = sbase + cs * STG_3;
                uint32_t sA = sb, sB = sb + TA_BYTES;
                int lrow = lane & 15, lkk = (lane >> 4) * 8;
#pragma unroll
                for (int ks = 0; ks < 4; ks++) {
                    int k = ks * 16 + lkk;
                    uint32_t a[2][4], b[2][4];
#pragma unroll
                    for (int mi = 0; mi < 2; mi++)
                        ldsm_x4(a[mi], sA + (uint32_t)((warp_m * 32 + mi * 16 + lrow) * SA64 + k) * 2);
#pragma unroll
                    for (int gj = 0; gj < 2; gj++)
                        ldsm_x4(b[gj], sB + (uint32_t)((warp_n * 32 + gj * 16 + lrow) * SA64 + k) * 2);
#pragma unroll
                    for (int mi = 0; mi < 2; mi++)
#pragma unroll
                    for (int gj = 0; gj < 2; gj++)
#pragma unroll
                    for (int hh = 0; hh < 2; hh++)
                        mma16816(acc[mi][gj * 2 + hh], a[mi], b[gj][hh], b[gj][2 + hh]);
                }
            }
            if (++cs == 3) cs = 0;
        }

        int gid = lane >> 2, q = lane & 3;
#pragma unroll
        for (int mi = 0; mi < 2; mi++)
#pragma unroll
        for (int nj = 0; nj < 4; nj++) {
            int m = m0 + warp_m * 32 + mi * 16 + gid;
            int n = n0 + warp_n * 32 + nj * 8 + q * 2;
            size_t off0 = ((size_t)(e * T_ + m)) * H_ + n;
            size_t off1 = ((size_t)(e * T_ + m + 8)) * H_ + n;
            *reinterpret_cast<float2*>(out + off0) = make_float2(acc[mi][nj][0], acc[mi][nj][1]);
            *reinterpret_cast<float2*>(out + off1) = make_float2(acc[mi][nj][2], acc[mi][nj][3]);
        }
    }
}

// ---------------- launch ----------------
extern "C" void kernel_launch(void* const* d_in, const int* in_sizes, int n_in,
                              void* d_out, int out_size) {
    const float* x    = (const float*)d_in[0];  // [8192, 1024]
    const float* acts = (const float*)d_in[1];  // [8192, 256]
    const float* wup  = (const float*)d_in[2];  // [8, 4096, 256]
    const float* v1   = (const float*)d_in[3];  // [8, 4096, 1024]
    const float* w2   = (const float*)d_in[4];  // [8, 4096, 1024]
    float* out = (float*)d_out;                 // [8192, 1024]

    cudaFuncSetAttribute(glu_kernel,   cudaFuncAttributeMaxDynamicSharedMemorySize, SMEM_GLU);
    cudaFuncSetAttribute(gemm3_kernel, cudaFuncAttributeMaxDynamicSharedMemorySize, SMEM_G3);

    conv_all<<<(int)(CB3 / 256), 256>>>(x, acts, wup, v1);
    {
        dim3 tg(F_ / 64, H_ / 32, E_);
        transpose_convert_w2<<<tg, dim3(32, 8)>>>(w2);
    }
    glu_kernel<<<NWORK, 256, SMEM_GLU>>>();
    gemm3_kernel<<<NWORK, 256, SMEM_G3>>>(out);
}

// round 6
// speedup vs baseline: 2.5033x; 1.0644x over previous
#include <cuda_runtime.h>
#include <cuda_fp16.h>
#include <cstdint>

// Problem constants
#define E_   8
#define T_   1024
#define H_   1024
#define F_   4096
#define DL_  256
#define NTOK (E_ * T_)   // 8192

// ---------------- device scratch ----------------
__device__ __half g_x  [(size_t)NTOK * H_];
__device__ __half g_a  [(size_t)NTOK * DL_];
__device__ __half g_wup[(size_t)E_ * F_ * DL_];
__device__ __half g_v1 [(size_t)E_ * F_ * H_];
__device__ __half g_h  [(size_t)E_ * T_ * F_];
__device__ __half g_w2t[(size_t)E_ * H_ * F_];

// ---------------- helpers ----------------
__device__ __forceinline__ uint32_t smem_u32(const void* p) {
    uint32_t a;
    asm("{ .reg .u64 t; cvta.to.shared.u64 t, %1; cvt.u32.u64 %0, t; }" : "=r"(a) : "l"(p));
    return a;
}
__device__ __forceinline__ void ldsm_x4(uint32_t (&r)[4], uint32_t addr) {
    asm volatile("ldmatrix.sync.aligned.m8n8.x4.shared.b16 {%0,%1,%2,%3}, [%4];"
        : "=r"(r[0]), "=r"(r[1]), "=r"(r[2]), "=r"(r[3]) : "r"(addr));
}
__device__ __forceinline__ void mma16816(float (&d)[4], const uint32_t (&a)[4],
                                         uint32_t b0, uint32_t b1) {
    asm volatile(
        "mma.sync.aligned.m16n8k16.row.col.f32.f16.f16.f32 "
        "{%0,%1,%2,%3}, {%4,%5,%6,%7}, {%8,%9}, {%0,%1,%2,%3};"
        : "+f"(d[0]), "+f"(d[1]), "+f"(d[2]), "+f"(d[3])
        : "r"(a[0]), "r"(a[1]), "r"(a[2]), "r"(a[3]), "r"(b0), "r"(b1));
}
__device__ __forceinline__ void cp16(uint32_t saddr, const void* g) {
    asm volatile("cp.async.cg.shared.global [%0], [%1], 16;" :: "r"(saddr), "l"(g));
}
#define CP_COMMIT() asm volatile("cp.async.commit_group;" ::: "memory")
#define CP_WAIT(N)  asm volatile("cp.async.wait_group %0;" :: "n"(N) : "memory")

__device__ __forceinline__ uint32_t pack_h2(__half a, __half b) {
    __half2 t; t.x = a; t.y = b;
    return *reinterpret_cast<uint32_t*>(&t);
}
__device__ __forceinline__ float silu(float a) { return a / (1.0f + __expf(-a)); }

// ---------------- fused conversion kernel (x, acts, wup, v1) ----------------
static constexpr size_t CB0 = (size_t)NTOK * H_ / 8;
static constexpr size_t CB1 = CB0 + (size_t)NTOK * DL_ / 8;
static constexpr size_t CB2 = CB1 + (size_t)E_ * F_ * DL_ / 8;
static constexpr size_t CB3 = CB2 + (size_t)E_ * F_ * H_ / 8;

__global__ void __launch_bounds__(256) conv_all(const float* __restrict__ x,
                                                const float* __restrict__ a,
                                                const float* __restrict__ w,
                                                const float* __restrict__ v) {
    size_t it = (size_t)blockIdx.x * 256 + threadIdx.x;
    const float* s; __half* d; size_t off;
    if      (it < CB0) { s = x; d = g_x;   off = it; }
    else if (it < CB1) { s = a; d = g_a;   off = it - CB0; }
    else if (it < CB2) { s = w; d = g_wup; off = it - CB1; }
    else               { s = v; d = g_v1;  off = it - CB2; }
    size_t i = off * 8;
    float4 v0 = *reinterpret_cast<const float4*>(s + i);
    float4 v1 = *reinterpret_cast<const float4*>(s + i + 4);
    uint4 o;
    o.x = pack_h2(__float2half_rn(v0.x), __float2half_rn(v0.y));
    o.y = pack_h2(__float2half_rn(v0.z), __float2half_rn(v0.w));
    o.z = pack_h2(__float2half_rn(v1.x), __float2half_rn(v1.y));
    o.w = pack_h2(__float2half_rn(v1.z), __float2half_rn(v1.w));
    *reinterpret_cast<uint4*>(d + i) = o;
}

// w2 [E,F,H] -> w2t [E,H,F] fp16, coalesced half2 stores
__global__ void __launch_bounds__(256) transpose_convert_w2(const float* __restrict__ w2) {
    __shared__ float tile[64][33];
    int e = blockIdx.z;
    int f0 = blockIdx.x * 64, h0 = blockIdx.y * 32;
    int tx = threadIdx.x, ty = threadIdx.y;  // 32 x 8
#pragma unroll
    for (int r = 0; r < 8; r++) {
        int fr = ty + r * 8;
        tile[fr][tx] = w2[((size_t)e * F_ + f0 + fr) * H_ + h0 + tx];
    }
    __syncthreads();
#pragma unroll
    for (int r = 0; r < 4; r++) {
        int h = ty + r * 8;
        uint32_t p = pack_h2(__float2half_rn(tile[2 * tx][h]),
                             __float2half_rn(tile[2 * tx + 1][h]));
        *reinterpret_cast<uint32_t*>(&g_w2t[((size_t)e * H_ + h0 + h) * F_ + f0 + 2 * tx]) = p;
    }
}

// ================= shared GEMM pieces =================
static constexpr int SA64 = 72;                    // row stride (fp16), 144 B
static constexpr int TA_BYTES = 128 * SA64 * 2;    // 18432 (128x64 tile)
static constexpr int STG   = 2 * TA_BYTES;         // A + B = 36864
static constexpr int SMEMB = 3 * STG;              // 110592
static constexpr int NWORK = 148;

// load a 128x64 fp16 K-major tile; 512 threads, 16B chunks (2 iters)
__device__ __forceinline__ void load_t64(uint32_t sdst, const __half* __restrict__ g,
                                         int ldg, int tid) {
#pragma unroll
    for (int i = 0; i < 2; i++) {
        int c = tid + i * 512;
        int row = c >> 3, col = (c & 7) * 8;
        cp16(sdst + (uint32_t)(row * SA64 + col) * 2, g + (size_t)row * ldg + col);
    }
}

// one K=64 stage for a 32x32 warp tile
__device__ __forceinline__ void mma_stage(float (&acc)[2][4][4], uint32_t sb,
                                          int warp_m, int warp_n, int lane) {
    uint32_t sA = sb, sB = sb + TA_BYTES;
    int lrow = lane & 15, lk = (lane >> 4) * 8;
#pragma unroll
    for (int ks = 0; ks < 4; ks++) {
        int k = ks * 16 + lk;
        uint32_t a[2][4], b[2][4];
#pragma unroll
        for (int mi = 0; mi < 2; mi++)
            ldsm_x4(a[mi], sA + (uint32_t)((warp_m * 32 + mi * 16 + lrow) * SA64 + k) * 2);
#pragma unroll
        for (int gj = 0; gj < 2; gj++)
            ldsm_x4(b[gj], sB + (uint32_t)((warp_n * 32 + gj * 16 + lrow) * SA64 + k) * 2);
#pragma unroll
        for (int mi = 0; mi < 2; mi++)
#pragma unroll
        for (int gj = 0; gj < 2; gj++)
#pragma unroll
        for (int hh = 0; hh < 2; hh++)
            mma16816(acc[mi][gj * 2 + hh], a[mi], b[gj][hh], b[gj][2 + hh]);
    }
}

// ================= GLU persistent: CTA 128x128, 512 thr (4x4 warps, warp 32x32) =================
static constexpr int NT_GLU = (T_ / 128) * (F_ / 128) * E_;   // 2048

__global__ void __launch_bounds__(512, 1) glu_kernel() {
    extern __shared__ char smem[];
    uint32_t sbase = smem_u32(smem);
    int tid = threadIdx.x, lane = tid & 31, wid = tid >> 5;
    int warp_m = wid & 3, warp_n = (wid >> 2) & 3;
    int bid = blockIdx.x;

    // loader state (2 chunks ahead, flat stream across tiles)
    int lt = bid, lk = 0, ls = 0;
    const __half *LAa, *LBw, *LAx, *LBv;
    auto set_lptrs = [&](int t) {
        int e = t >> 8, r = t & 255;
        int m0 = (r >> 5) * 128, f0 = (r & 31) * 128;
        LAa = g_a   + (size_t)(e * T_ + m0) * DL_;
        LBw = g_wup + ((size_t)e * F_ + f0) * DL_;
        LAx = g_x   + (size_t)(e * T_ + m0) * H_;
        LBv = g_v1  + ((size_t)e * F_ + f0) * H_;
    };
    if (lt < NT_GLU) set_lptrs(lt);
    auto issue = [&]() {
        uint32_t sb = sbase + ls * STG;
        if (lt < NT_GLU) {
            if (lk < 4) {
                load_t64(sb,            LAa + lk * 64, DL_, tid);
                load_t64(sb + TA_BYTES, LBw + lk * 64, DL_, tid);
            } else {
                int k2 = lk - 4;
                load_t64(sb,            LAx + k2 * 64, H_, tid);
                load_t64(sb + TA_BYTES, LBv + k2 * 64, H_, tid);
            }
        }
        CP_COMMIT();   // empty group past end keeps wait counts uniform
        if (++ls == 3) ls = 0;
        if (++lk == 20) { lk = 0; lt += NWORK; if (lt < NT_GLU) set_lptrs(lt); }
    };
    issue(); issue();

    int cs = 0;
    for (int ct = bid; ct < NT_GLU; ct += NWORK) {
        int e = ct >> 8, r = ct & 255;
        int m0 = (r >> 5) * 128, f0 = (r & 31) * 128;

        float acc1[2][4][4], acc2[2][4][4];
#pragma unroll
        for (int i = 0; i < 2; i++)
#pragma unroll
            for (int j = 0; j < 4; j++)
#pragma unroll
                for (int k = 0; k < 4; k++) { acc1[i][j][k] = 0.f; acc2[i][j][k] = 0.f; }

        for (int kt = 0; kt < 20; kt++) {
            CP_WAIT(1);
            __syncthreads();
            issue();
            if (kt < 4) mma_stage(acc1, sbase + cs * STG, warp_m, warp_n, lane);
            else        mma_stage(acc2, sbase + cs * STG, warp_m, warp_n, lane);
            if (++cs == 3) cs = 0;
        }

        // epilogue: h = silu(acc1) * acc2 -> fp16 (overlaps next tile's loads)
        int gid = lane >> 2, q = lane & 3;
#pragma unroll
        for (int mi = 0; mi < 2; mi++)
#pragma unroll
        for (int nj = 0; nj < 4; nj++) {
            int m = m0 + warp_m * 32 + mi * 16 + gid;
            int n = f0 + warp_n * 32 + nj * 8 + q * 2;
            float s0 = silu(acc1[mi][nj][0]) * acc2[mi][nj][0];
            float s1 = silu(acc1[mi][nj][1]) * acc2[mi][nj][1];
            float s2 = silu(acc1[mi][nj][2]) * acc2[mi][nj][2];
            float s3 = silu(acc1[mi][nj][3]) * acc2[mi][nj][3];
            size_t off0 = ((size_t)(e * T_ + m)) * F_ + n;
            size_t off1 = ((size_t)(e * T_ + m + 8)) * F_ + n;
            *reinterpret_cast<uint32_t*>(g_h + off0) = pack_h2(__float2half_rn(s0), __float2half_rn(s1));
            *reinterpret_cast<uint32_t*>(g_h + off1) = pack_h2(__float2half_rn(s2), __float2half_rn(s3));
        }
    }
}

// ================= GEMM3 persistent: CTA 128x128, 512 thr (4x4 warps, warp 32x32) =================
static constexpr int NT_G3  = (T_ / 128) * (H_ / 128) * E_;  // 512
static constexpr int NKC_G3 = F_ / 64;                       // 64

__global__ void __launch_bounds__(512, 1) gemm3_kernel(float* __restrict__ out) {
    extern __shared__ char smem[];
    uint32_t sbase = smem_u32(smem);
    int tid = threadIdx.x, lane = tid & 31, wid = tid >> 5;
    int warp_m = wid & 3, warp_n = (wid >> 2) & 3;
    int bid = blockIdx.x;

    int lt = bid, lk = 0, ls = 0;
    const __half *LA, *LB;
    auto set_lptrs = [&](int t) {
        int e = t >> 6, r = t & 63;
        int m0 = (r >> 3) * 128, n0 = (r & 7) * 128;
        LA = g_h   + (size_t)(e * T_ + m0) * F_;
        LB = g_w2t + ((size_t)e * H_ + n0) * F_;
    };
    if (lt < NT_G3) set_lptrs(lt);
    auto issue = [&]() {
        uint32_t sb = sbase + ls * STG;
        if (lt < NT_G3) {
            load_t64(sb,            LA + lk * 64, F_, tid);
            load_t64(sb + TA_BYTES, LB + lk * 64, F_, tid);
        }
        CP_COMMIT();
        if (++ls == 3) ls = 0;
        if (++lk == NKC_G3) { lk = 0; lt += NWORK; if (lt < NT_G3) set_lptrs(lt); }
    };
    issue(); issue();

    int cs = 0;
    for (int ct = bid; ct < NT_G3; ct += NWORK) {
        int e = ct >> 6, r = ct & 63;
        int m0 = (r >> 3) * 128, n0 = (r & 7) * 128;

        float acc[2][4][4];
#pragma unroll
        for (int i = 0; i < 2; i++)
#pragma unroll
            for (int j = 0; j < 4; j++)
#pragma unroll
                for (int k = 0; k < 4; k++) acc[i][j][k] = 0.f;

        for (int kt = 0; kt < NKC_G3; kt++) {
            CP_WAIT(1);
            __syncthreads();
            issue();
            mma_stage(acc, sbase + cs * STG, warp_m, warp_n, lane);
            if (++cs == 3) cs = 0;
        }

        int gid = lane >> 2, q = lane & 3;
#pragma unroll
        for (int mi = 0; mi < 2; mi++)
#pragma unroll
        for (int nj = 0; nj < 4; nj++) {
            int m = m0 + warp_m * 32 + mi * 16 + gid;
            int n = n0 + warp_n * 32 + nj * 8 + q * 2;
            size_t off0 = ((size_t)(e * T_ + m)) * H_ + n;
            size_t off1 = ((size_t)(e * T_ + m + 8)) * H_ + n;
            *reinterpret_cast<float2*>(out + off0) = make_float2(acc[mi][nj][0], acc[mi][nj][1]);
            *reinterpret_cast<float2*>(out + off1) = make_float2(acc[mi][nj][2], acc[mi][nj][3]);
        }
    }
}

// ---------------- launch ----------------
extern "C" void kernel_launch(void* const* d_in, const int* in_sizes, int n_in,
                              void* d_out, int out_size) {
    const float* x    = (const float*)d_in[0];  // [8192, 1024]
    const float* acts = (const float*)d_in[1];  // [8192, 256]
    const float* wup  = (const float*)d_in[2];  // [8, 4096, 256]
    const float* v1   = (const float*)d_in[3];  // [8, 4096, 1024]
    const float* w2   = (const float*)d_in[4];  // [8, 4096, 1024]
    float* out = (float*)d_out;                 // [8192, 1024]

    cudaFuncSetAttribute(glu_kernel,   cudaFuncAttributeMaxDynamicSharedMemorySize, SMEMB);
    cudaFuncSetAttribute(gemm3_kernel, cudaFuncAttributeMaxDynamicSharedMemorySize, SMEMB);

    conv_all<<<(int)(CB3 / 256), 256>>>(x, acts, wup, v1);
    {
        dim3 tg(F_ / 64, H_ / 32, E_);
        transpose_convert_w2<<<tg, dim3(32, 8)>>>(w2);
    }
    glu_kernel<<<NWORK, 512, SMEMB>>>();
    gemm3_kernel<<<NWORK, 512, SMEMB>>>(out);
}

// round 7
// speedup vs baseline: 2.8121x; 1.1234x over previous
#include <cuda_runtime.h>
#include <cuda_fp16.h>
#include <cstdint>

// Problem constants
#define E_   8
#define T_   1024
#define H_   1024
#define F_   4096
#define DL_  256
#define NTOK (E_ * T_)   // 8192

// ---------------- device scratch ----------------
__device__ __half g_x  [(size_t)NTOK * H_];
__device__ __half g_a  [(size_t)NTOK * DL_];
__device__ __half g_wup[(size_t)E_ * F_ * DL_];
__device__ __half g_v1 [(size_t)E_ * F_ * H_];
__device__ __half g_h  [(size_t)E_ * T_ * F_];
__device__ __half g_w2t[(size_t)E_ * H_ * F_];

// ---------------- helpers ----------------
__device__ __forceinline__ uint32_t smem_u32(const void* p) {
    uint32_t a;
    asm("{ .reg .u64 t; cvta.to.shared.u64 t, %1; cvt.u32.u64 %0, t; }" : "=r"(a) : "l"(p));
    return a;
}
__device__ __forceinline__ void ldsm_x4(uint32_t (&r)[4], uint32_t addr) {
    asm volatile("ldmatrix.sync.aligned.m8n8.x4.shared.b16 {%0,%1,%2,%3}, [%4];"
        : "=r"(r[0]), "=r"(r[1]), "=r"(r[2]), "=r"(r[3]) : "r"(addr));
}
__device__ __forceinline__ void mma16816(float (&d)[4], const uint32_t (&a)[4],
                                         uint32_t b0, uint32_t b1) {
    asm volatile(
        "mma.sync.aligned.m16n8k16.row.col.f32.f16.f16.f32 "
        "{%0,%1,%2,%3}, {%4,%5,%6,%7}, {%8,%9}, {%0,%1,%2,%3};"
        : "+f"(d[0]), "+f"(d[1]), "+f"(d[2]), "+f"(d[3])
        : "r"(a[0]), "r"(a[1]), "r"(a[2]), "r"(a[3]), "r"(b0), "r"(b1));
}
__device__ __forceinline__ void cp16(uint32_t saddr, const void* g) {
    asm volatile("cp.async.cg.shared.global [%0], [%1], 16;" :: "r"(saddr), "l"(g));
}
#define CP_COMMIT() asm volatile("cp.async.commit_group;" ::: "memory")
#define CP_WAIT(N)  asm volatile("cp.async.wait_group %0;" :: "n"(N) : "memory")

__device__ __forceinline__ uint32_t pack_h2(__half a, __half b) {
    __half2 t; t.x = a; t.y = b;
    return *reinterpret_cast<uint32_t*>(&t);
}
__device__ __forceinline__ float silu(float a) { return a / (1.0f + __expf(-a)); }

// ---------------- fused conversion kernel (x, acts, wup, v1) ----------------
static constexpr size_t CB0 = (size_t)NTOK * H_ / 8;
static constexpr size_t CB1 = CB0 + (size_t)NTOK * DL_ / 8;
static constexpr size_t CB2 = CB1 + (size_t)E_ * F_ * DL_ / 8;
static constexpr size_t CB3 = CB2 + (size_t)E_ * F_ * H_ / 8;

__global__ void __launch_bounds__(256) conv_all(const float* __restrict__ x,
                                                const float* __restrict__ a,
                                                const float* __restrict__ w,
                                                const float* __restrict__ v) {
    size_t it = (size_t)blockIdx.x * 256 + threadIdx.x;
    const float* s; __half* d; size_t off;
    if      (it < CB0) { s = x; d = g_x;   off = it; }
    else if (it < CB1) { s = a; d = g_a;   off = it - CB0; }
    else if (it < CB2) { s = w; d = g_wup; off = it - CB1; }
    else               { s = v; d = g_v1;  off = it - CB2; }
    size_t i = off * 8;
    float4 v0 = *reinterpret_cast<const float4*>(s + i);
    float4 v1 = *reinterpret_cast<const float4*>(s + i + 4);
    uint4 o;
    o.x = pack_h2(__float2half_rn(v0.x), __float2half_rn(v0.y));
    o.y = pack_h2(__float2half_rn(v0.z), __float2half_rn(v0.w));
    o.z = pack_h2(__float2half_rn(v1.x), __float2half_rn(v1.y));
    o.w = pack_h2(__float2half_rn(v1.z), __float2half_rn(v1.w));
    *reinterpret_cast<uint4*>(d + i) = o;
}

// w2 [E,F,H] -> w2t [E,H,F] fp16, coalesced half2 stores
__global__ void __launch_bounds__(256) transpose_convert_w2(const float* __restrict__ w2) {
    __shared__ float tile[64][33];
    int e = blockIdx.z;
    int f0 = blockIdx.x * 64, h0 = blockIdx.y * 32;
    int tx = threadIdx.x, ty = threadIdx.y;  // 32 x 8
#pragma unroll
    for (int r = 0; r < 8; r++) {
        int fr = ty + r * 8;
        tile[fr][tx] = w2[((size_t)e * F_ + f0 + fr) * H_ + h0 + tx];
    }
    __syncthreads();
#pragma unroll
    for (int r = 0; r < 4; r++) {
        int h = ty + r * 8;
        uint32_t p = pack_h2(__float2half_rn(tile[2 * tx][h]),
                             __float2half_rn(tile[2 * tx + 1][h]));
        *reinterpret_cast<uint32_t*>(&g_w2t[((size_t)e * H_ + h0 + h) * F_ + f0 + 2 * tx]) = p;
    }
}

// ================= shared GEMM pieces: CTA 128(m) x 256(n), 512 thr, warp 32x64 =================
static constexpr int SA64 = 72;                    // row stride (fp16), 144 B
static constexpr int A_BYTES = 128 * SA64 * 2;     // 18432
static constexpr int B_BYTES = 256 * SA64 * 2;     // 36864
static constexpr int STG   = A_BYTES + B_BYTES;    // 55296
static constexpr int SMEMB = 3 * STG;              // 165888
static constexpr int NWORK = 148;

// load ROWSx64 fp16 K-major tile; 512 threads, 16B chunks
template <int ROWS>
__device__ __forceinline__ void load_rows(uint32_t sdst, const __half* __restrict__ g,
                                          int ldg, int tid) {
#pragma unroll
    for (int i = 0; i < ROWS * 8 / 512; i++) {
        int c = tid + i * 512;
        int row = c >> 3, col = (c & 7) * 8;
        cp16(sdst + (uint32_t)(row * SA64 + col) * 2, g + (size_t)row * ldg + col);
    }
}

// one K=64 stage for a 32x64 warp tile; B ldsm live-range kept short (4 regs)
__device__ __forceinline__ void mma_3264(float (&acc)[2][8][4], uint32_t sb,
                                         int warp_m, int warp_n, int lane) {
    uint32_t sA = sb, sB = sb + A_BYTES;
    int lrow = lane & 15, lk = (lane >> 4) * 8;
#pragma unroll
    for (int ks = 0; ks < 4; ks++) {
        int k = ks * 16 + lk;
        uint32_t a[2][4];
#pragma unroll
        for (int mi = 0; mi < 2; mi++)
            ldsm_x4(a[mi], sA + (uint32_t)((warp_m * 32 + mi * 16 + lrow) * SA64 + k) * 2);
#pragma unroll
        for (int gj = 0; gj < 4; gj++) {
            uint32_t b[4];
            ldsm_x4(b, sB + (uint32_t)((warp_n * 64 + gj * 16 + lrow) * SA64 + k) * 2);
            mma16816(acc[0][gj * 2 + 0], a[0], b[0], b[2]);
            mma16816(acc[0][gj * 2 + 1], a[0], b[1], b[3]);
            mma16816(acc[1][gj * 2 + 0], a[1], b[0], b[2]);
            mma16816(acc[1][gj * 2 + 1], a[1], b[1], b[3]);
        }
    }
}

// ================= GLU persistent: tile 128x256 =================
static constexpr int NT_GLU = (T_ / 128) * (F_ / 256) * E_;   // 1024
static constexpr int NKC_GLU = 4 + 16;                        // acts/wup then x/v1

__global__ void __launch_bounds__(512, 1) glu_kernel() {
    extern __shared__ char smem[];
    uint32_t sbase = smem_u32(smem);
    int tid = threadIdx.x, lane = tid & 31, wid = tid >> 5;
    int warp_m = wid & 3, warp_n = wid >> 2;   // 4 x 4
    int bid = blockIdx.x;

    // loader state (2 chunks ahead, flat stream across tiles)
    int lt = bid, lk = 0, ls = 0;
    const __half *LAa, *LBw, *LAx, *LBv;
    auto set_lptrs = [&](int t) {
        int e = t >> 7, r = t & 127;
        int m0 = (r >> 4) * 128, f0 = (r & 15) * 256;
        LAa = g_a   + (size_t)(e * T_ + m0) * DL_;
        LBw = g_wup + ((size_t)e * F_ + f0) * DL_;
        LAx = g_x   + (size_t)(e * T_ + m0) * H_;
        LBv = g_v1  + ((size_t)e * F_ + f0) * H_;
    };
    if (lt < NT_GLU) set_lptrs(lt);
    auto issue = [&]() {
        uint32_t sb = sbase + ls * STG;
        if (lt < NT_GLU) {
            if (lk < 4) {
                load_rows<128>(sb,           LAa + lk * 64, DL_, tid);
                load_rows<256>(sb + A_BYTES, LBw + lk * 64, DL_, tid);
            } else {
                int k2 = lk - 4;
                load_rows<128>(sb,           LAx + k2 * 64, H_, tid);
                load_rows<256>(sb + A_BYTES, LBv + k2 * 64, H_, tid);
            }
        }
        CP_COMMIT();   // empty group past end keeps wait counts uniform
        if (++ls == 3) ls = 0;
        if (++lk == NKC_GLU) { lk = 0; lt += NWORK; if (lt < NT_GLU) set_lptrs(lt); }
    };
    issue(); issue();

    int cs = 0;
    for (int ct = bid; ct < NT_GLU; ct += NWORK) {
        int e = ct >> 7, r = ct & 127;
        int m0 = (r >> 4) * 128, f0 = (r & 15) * 256;

        float acc[2][8][4];
        uint32_t x1h[2][8][2];   // packed x1 (phase A result), 32 regs
#pragma unroll
        for (int i = 0; i < 2; i++)
#pragma unroll
            for (int j = 0; j < 8; j++)
#pragma unroll
                for (int k = 0; k < 4; k++) acc[i][j][k] = 0.f;

        for (int kt = 0; kt < NKC_GLU; kt++) {
            CP_WAIT(1);
            __syncthreads();
            issue();
            if (kt == 4) {
                // phase A done: pack x1 to fp16, reset acc for phase B
#pragma unroll
                for (int mi = 0; mi < 2; mi++)
#pragma unroll
                for (int nj = 0; nj < 8; nj++) {
                    x1h[mi][nj][0] = pack_h2(__float2half_rn(acc[mi][nj][0]),
                                             __float2half_rn(acc[mi][nj][1]));
                    x1h[mi][nj][1] = pack_h2(__float2half_rn(acc[mi][nj][2]),
                                             __float2half_rn(acc[mi][nj][3]));
                    acc[mi][nj][0] = 0.f; acc[mi][nj][1] = 0.f;
                    acc[mi][nj][2] = 0.f; acc[mi][nj][3] = 0.f;
                }
            }
            mma_3264(acc, sbase + cs * STG, warp_m, warp_n, lane);
            if (++cs == 3) cs = 0;
        }

        // epilogue: h = silu(x1) * acc2 -> fp16 (overlaps next tile's loads)
        int gid = lane >> 2, q = lane & 3;
#pragma unroll
        for (int mi = 0; mi < 2; mi++)
#pragma unroll
        for (int nj = 0; nj < 8; nj++) {
            int m = m0 + warp_m * 32 + mi * 16 + gid;
            int n = f0 + warp_n * 64 + nj * 8 + q * 2;
            __half2 p0 = *reinterpret_cast<__half2*>(&x1h[mi][nj][0]);
            __half2 p1 = *reinterpret_cast<__half2*>(&x1h[mi][nj][1]);
            float s0 = silu(__half2float(p0.x)) * acc[mi][nj][0];
            float s1 = silu(__half2float(p0.y)) * acc[mi][nj][1];
            float s2 = silu(__half2float(p1.x)) * acc[mi][nj][2];
            float s3 = silu(__half2float(p1.y)) * acc[mi][nj][3];
            size_t off0 = ((size_t)(e * T_ + m)) * F_ + n;
            size_t off1 = ((size_t)(e * T_ + m + 8)) * F_ + n;
            *reinterpret_cast<uint32_t*>(g_h + off0) = pack_h2(__float2half_rn(s0), __float2half_rn(s1));
            *reinterpret_cast<uint32_t*>(g_h + off1) = pack_h2(__float2half_rn(s2), __float2half_rn(s3));
        }
    }
}

// ================= GEMM3 persistent: tile 128x256, K=4096 =================
static constexpr int NT_G3  = (T_ / 128) * (H_ / 256) * E_;  // 256
static constexpr int NKC_G3 = F_ / 64;                       // 64

__global__ void __launch_bounds__(512, 1) gemm3_kernel(float* __restrict__ out) {
    extern __shared__ char smem[];
    uint32_t sbase = smem_u32(smem);
    int tid = threadIdx.x, lane = tid & 31, wid = tid >> 5;
    int warp_m = wid & 3, warp_n = wid >> 2;   // 4 x 4
    int bid = blockIdx.x;

    int lt = bid, lk = 0, ls = 0;
    const __half *LA, *LB;
    auto set_lptrs = [&](int t) {
        int e = t >> 5, r = t & 31;
        int m0 = (r >> 2) * 128, n0 = (r & 3) * 256;
        LA = g_h   + (size_t)(e * T_ + m0) * F_;
        LB = g_w2t + ((size_t)e * H_ + n0) * F_;
    };
    if (lt < NT_G3) set_lptrs(lt);
    auto issue = [&]() {
        uint32_t sb = sbase + ls * STG;
        if (lt < NT_G3) {
            load_rows<128>(sb,           LA + lk * 64, F_, tid);
            load_rows<256>(sb + A_BYTES, LB + lk * 64, F_, tid);
        }
        CP_COMMIT();
        if (++ls == 3) ls = 0;
        if (++lk == NKC_G3) { lk = 0; lt += NWORK; if (lt < NT_G3) set_lptrs(lt); }
    };
    issue(); issue();

    int cs = 0;
    for (int ct = bid; ct < NT_G3; ct += NWORK) {
        int e = ct >> 5, r = ct & 31;
        int m0 = (r >> 2) * 128, n0 = (r & 3) * 256;

        float acc[2][8][4];
#pragma unroll
        for (int i = 0; i < 2; i++)
#pragma unroll
            for (int j = 0; j < 8; j++)
#pragma unroll
                for (int k = 0; k < 4; k++) acc[i][j][k] = 0.f;

        for (int kt = 0; kt < NKC_G3; kt++) {
            CP_WAIT(1);
            __syncthreads();
            issue();
            mma_3264(acc, sbase + cs * STG, warp_m, warp_n, lane);
            if (++cs == 3) cs = 0;
        }

        int gid = lane >> 2, q = lane & 3;
#pragma unroll
        for (int mi = 0; mi < 2; mi++)
#pragma unroll
        for (int nj = 0; nj < 8; nj++) {
            int m = m0 + warp_m * 32 + mi * 16 + gid;
            int n = n0 + warp_n * 64 + nj * 8 + q * 2;
            size_t off0 = ((size_t)(e * T_ + m)) * H_ + n;
            size_t off1 = ((size_t)(e * T_ + m + 8)) * H_ + n;
            *reinterpret_cast<float2*>(out + off0) = make_float2(acc[mi][nj][0], acc[mi][nj][1]);
            *reinterpret_cast<float2*>(out + off1) = make_float2(acc[mi][nj][2], acc[mi][nj][3]);
        }
    }
}

// ---------------- launch ----------------
extern "C" void kernel_launch(void* const* d_in, const int* in_sizes, int n_in,
                              void* d_out, int out_size) {
    const float* x    = (const float*)d_in[0];  // [8192, 1024]
    const float* acts = (const float*)d_in[1];  // [8192, 256]
    const float* wup  = (const float*)d_in[2];  // [8, 4096, 256]
    const float* v1   = (const float*)d_in[3];  // [8, 4096, 1024]
    const float* w2   = (const float*)d_in[4];  // [8, 4096, 1024]
    float* out = (float*)d_out;                 // [8192, 1024]

    cudaFuncSetAttribute(glu_kernel,   cudaFuncAttributeMaxDynamicSharedMemorySize, SMEMB);
    cudaFuncSetAttribute(gemm3_kernel, cudaFuncAttributeMaxDynamicSharedMemorySize, SMEMB);

    conv_all<<<(int)(CB3 / 256), 256>>>(x, acts, wup, v1);
    {
        dim3 tg(F_ / 64, H_ / 32, E_);
        transpose_convert_w2<<<tg, dim3(32, 8)>>>(w2);
    }
    glu_kernel<<<NWORK, 512, SMEMB>>>();
    gemm3_kernel<<<NWORK, 512, SMEMB>>>(out);
}